// round 1
// baseline (speedup 1.0000x reference)
#include <cuda_runtime.h>

#define NBODY 4194304
#define HALF_PI 1.57079632679489662f

// Scratch (static __device__ globals — no allocations anywhere).
__device__ float4        g_w[NBODY];       // {abs_x, abs_y, mass, pad} per body
__device__ unsigned char g_touched[NBODY]; // scatter target flag
__device__ double        g_sums[3];        // sum(m*ax), sum(m*ay), sum(m)

// ---------------------------------------------------------------------------
// K1: per-body coalesced precompute of world-space anchor point f(b) and mass.
// Also zeroes the touched flags and the accumulators (thread 0).
// ---------------------------------------------------------------------------
__global__ void __launch_bounds__(256)
k1_prepare(const float2* __restrict__ pos,
           const float*  __restrict__ ang,
           const float*  __restrict__ mass,
           const float2* __restrict__ from_pos,
           const float2* __restrict__ to_pos,
           int n, int nc) {
    int b = blockIdx.x * blockDim.x + threadIdx.x;
    if (b == 0) { g_sums[0] = 0.0; g_sums[1] = 0.0; g_sums[2] = 0.0; }
    if (b >= n) return;

    float2 p = pos[b];
    float  a = ang[b] - HALF_PI;
    float  m = mass[b];
    // rel_positions = concat(from_pos, to_pos), indexed by BODY index (source quirk)
    float2 r = (b < nc) ? from_pos[b] : to_pos[b - nc];

    float s, c;
    sincosf(a, &s, &c);
    float ax = (c * r.x - s * r.y) + p.x;
    float ay = (s * r.x + c * r.y) + p.y;

    g_w[b]       = make_float4(ax, ay, m, 0.0f);
    g_touched[b] = 0;
}

// ---------------------------------------------------------------------------
// K2: per-endpoint reduction. One 16B aligned gather per endpoint (1 sector),
// plain idempotent byte store for the touched flag, hierarchical reduction
// into double accumulators (3 atomics per block, 1184 blocks -> no contention).
// ---------------------------------------------------------------------------
__global__ void __launch_bounds__(256)
k2_reduce(const int* __restrict__ fromb,
          const int* __restrict__ tob,
          int nc) {
    const int total  = 2 * nc;
    const int stride = gridDim.x * blockDim.x;

    float sx = 0.0f, sy = 0.0f, sm = 0.0f;
    for (int i = blockIdx.x * blockDim.x + threadIdx.x; i < total; i += stride) {
        int idx = (i < nc) ? fromb[i] : tob[i - nc];
        g_touched[idx] = 1;                    // race-free: everyone writes 1
        float4 w = __ldg(&g_w[idx]);           // single 32B sector
        sx += w.z * w.x;
        sy += w.z * w.y;
        sm += w.z;
    }

    // warp reduce
    #pragma unroll
    for (int o = 16; o > 0; o >>= 1) {
        sx += __shfl_down_sync(0xffffffffu, sx, o);
        sy += __shfl_down_sync(0xffffffffu, sy, o);
        sm += __shfl_down_sync(0xffffffffu, sm, o);
    }

    __shared__ float ssx[8], ssy[8], ssm[8];
    int wid = threadIdx.x >> 5, lid = threadIdx.x & 31;
    if (lid == 0) { ssx[wid] = sx; ssy[wid] = sy; ssm[wid] = sm; }
    __syncthreads();

    if (threadIdx.x == 0) {
        float tx = 0.0f, ty = 0.0f, tm = 0.0f;
        int nw = blockDim.x >> 5;
        #pragma unroll
        for (int w = 0; w < 8; ++w) {
            if (w < nw) { tx += ssx[w]; ty += ssy[w]; tm += ssm[w]; }
        }
        atomicAdd(&g_sums[0], (double)tx);
        atomicAdd(&g_sums[1], (double)ty);
        atomicAdd(&g_sums[2], (double)tm);
    }
}

// ---------------------------------------------------------------------------
// K3: per-body coalesced epilogue. target is uniform (broadcast loads),
// impulse multiplied by the touched flag to avoid divergence.
// ---------------------------------------------------------------------------
__global__ void __launch_bounds__(256)
k3_apply(const float2* __restrict__ vel,
         const float*  __restrict__ stiff,
         float2*       __restrict__ out,
         int n) {
    int b = blockIdx.x * blockDim.x + threadIdx.x;
    if (b >= n) return;

    float smf = (float)g_sums[2];
    float tx  = (float)g_sums[0] / smf;
    float ty  = (float)g_sums[1] / smf;
    float sdt = stiff[0] * 0.01f;   // stiffness * DT

    float4 w = g_w[b];
    float  t = (float)g_touched[b];
    float2 v = vel[b];
    v.x += t * sdt * (tx - w.x);
    v.y += t * sdt * (ty - w.y);
    out[b] = v;
}

// ---------------------------------------------------------------------------
// Input order (metadata): from_bodies, to_bodies, from_bodies_position,
// to_bodies_position, stiffness, position, angle, mass, velocity
// ---------------------------------------------------------------------------
extern "C" void kernel_launch(void* const* d_in, const int* in_sizes, int n_in,
                              void* d_out, int out_size) {
    const int*    fromb = (const int*)   d_in[0];
    const int*    tob   = (const int*)   d_in[1];
    const float2* fpos  = (const float2*)d_in[2];
    const float2* tpos  = (const float2*)d_in[3];
    const float*  stiff = (const float*) d_in[4];
    const float2* pos   = (const float2*)d_in[5];
    const float*  ang   = (const float*) d_in[6];
    const float*  mass  = (const float*) d_in[7];
    const float2* vel   = (const float2*)d_in[8];

    int nc = in_sizes[0];          // NC constraint endpoints per side
    int n  = in_sizes[6];          // N bodies (angle element count)
    if (n > NBODY) n = NBODY;      // scratch bound guard

    const int tpb = 256;
    int nblk = (n + tpb - 1) / tpb;

    k1_prepare<<<nblk, tpb>>>(pos, ang, mass, fpos, tpos, n, nc);
    k2_reduce<<<1184, tpb>>>(fromb, tob, nc);
    k3_apply<<<nblk, tpb>>>(vel, stiff, (float2*)d_out, n);
}